// round 4
// baseline (speedup 1.0000x reference)
#include <cuda_runtime.h>
#include <math.h>

#define DD      64
#define TRI     2080          // 64*65/2
#define NT      160           // threads per SYRK block (144 compute)
#define CHUNK   32            // nodes per smem chunk
#define RSTRIDE 68            // padded row stride (floats)
#define NSL     4             // k-slices per tile

#define MAX_M  100000
#define MAX_G  1024

typedef unsigned long long u64;

__device__ float g_imp[MAX_M];
__device__ int   g_start[MAX_G + 1];
__device__ int   g_is64;

// ---------------------------------------------------------------------------
// Detect int64 vs int32 batch buffer (odd 32-bit words all zero => int64).
// ---------------------------------------------------------------------------
__global__ void k_detect(const int* __restrict__ b32, int M) {
    __shared__ int anynz;
    if (threadIdx.x == 0) anynz = 0;
    __syncthreads();
    int nwords = 2 * M;
    if (nwords > 4096) nwords = 4096;
    if (nwords > M) nwords = M;    // never exceed int32 lower-bound size
    for (int i = 2 * threadIdx.x + 1; i < nwords; i += 2 * blockDim.x)
        if (b32[i] != 0) anynz = 1;
    __syncthreads();
    if (threadIdx.x == 0) g_is64 = (anynz == 0) ? 1 : 0;
}

// ---------------------------------------------------------------------------
// Segment boundaries from sorted batch.
// ---------------------------------------------------------------------------
__global__ void k_bounds(const void* __restrict__ batch, int M, int G) {
    int m = blockIdx.x * blockDim.x + threadIdx.x;
    if (m >= M) return;
    int is64 = g_is64;
    const int* b32 = (const int*)batch;
    const long long* b64 = (const long long*)batch;
    int b  = is64 ? (int)b64[m] : b32[m];
    int pb;
    if (m == 0) pb = -1;
    else        pb = is64 ? (int)b64[m - 1] : b32[m - 1];
    if (b  < 0) b  = 0; if (b  >= G) b  = G - 1;
    if (pb < -1) pb = -1; if (pb >= G) pb = G - 1;
    for (int g = pb + 1; g <= b; ++g) g_start[g] = m;
    if (m == M - 1) {
        for (int g = b + 1; g <= G; ++g) g_start[g] = M;
    }
}

// ---------------------------------------------------------------------------
// imp[m] = dot(x[m], w) + bias. One warp per node.
// ---------------------------------------------------------------------------
__global__ void k_imp(const float* __restrict__ x, const float* __restrict__ w,
                      const float* __restrict__ bias, int M) {
    int gwarp = (blockIdx.x * blockDim.x + threadIdx.x) >> 5;
    int lane  = threadIdx.x & 31;
    if (gwarp >= M) return;
    const float* xr = x + (size_t)gwarp * DD;
    float v = xr[lane] * __ldg(w + lane) + xr[lane + 32] * __ldg(w + lane + 32);
#pragma unroll
    for (int o = 16; o; o >>= 1) v += __shfl_xor_sync(0xFFFFFFFFu, v, o);
    if (lane == 0) g_imp[gwarp] = v + __ldg(bias);
}

// ---------------------------------------------------------------------------
// Per-graph softmax + weighted SYRK (FFMA2), triu writeout.
// 36 upper 8x8 tiles x 4 k-slices = 144 compute threads.
// smem rows hold sqrt(e_k) * x_k so a.b carries e_k automatically.
// ---------------------------------------------------------------------------
__global__ __launch_bounds__(NT)
void k_syrk(const float* __restrict__ x, float* __restrict__ out, int G) {
    __shared__ float sz[2][CHUNK * RSTRIDE];
    __shared__ float sred[NT / 32];
    __shared__ float sbr[2];

    int g   = blockIdx.x;
    int tid = threadIdx.x;
    int s   = g_start[g];
    int n   = g_start[g + 1] - s;

    // ---- segment max ----
    float mx = -3.402823466e38f;
    for (int i = tid; i < n; i += NT) mx = fmaxf(mx, g_imp[s + i]);
#pragma unroll
    for (int o = 16; o; o >>= 1) mx = fmaxf(mx, __shfl_xor_sync(0xFFFFFFFFu, mx, o));
    if ((tid & 31) == 0) sred[tid >> 5] = mx;
    __syncthreads();
    if (tid == 0) {
        float m2 = sred[0];
#pragma unroll
        for (int i = 1; i < NT / 32; ++i) m2 = fmaxf(m2, sred[i]);
        sbr[0] = m2;
    }
    __syncthreads();
    mx = sbr[0];

    // ---- segment denom ----
    float sum = 0.f;
    for (int i = tid; i < n; i += NT) sum += expf(g_imp[s + i] - mx);
#pragma unroll
    for (int o = 16; o; o >>= 1) sum += __shfl_xor_sync(0xFFFFFFFFu, sum, o);
    if ((tid & 31) == 0) sred[tid >> 5] = sum;
    __syncthreads();
    if (tid == 0) {
        float t = 0.f;
#pragma unroll
        for (int i = 0; i < NT / 32; ++i) t += sred[i];
        sbr[1] = (n > 0) ? (1.0f / t) : 0.0f;
    }
    __syncthreads();
    float inv_denom = sbr[1];

    // ---- tile mapping: tile = tid>>2 in [0,36), slice = tid&3 ----
    bool isComp = (tid < 144);
    int  tile   = tid >> 2;
    int  slice  = tid & 3;
    int  ti = 0, tmp = tile;
#pragma unroll
    for (int r = 0; r < 8; ++r) {
        int rl = 8 - r;
        if (ti == r && tmp >= rl) { tmp -= rl; ti = r + 1; }
    }
    int tj = ti + tmp;

    u64 acc2[8][4];
#pragma unroll
    for (int i = 0; i < 8; ++i)
#pragma unroll
        for (int jp = 0; jp < 4; ++jp) acc2[i][jp] = 0ULL;

    int nch = (n + CHUNK - 1) / CHUNK;

    // ---- chunk loader: rows scaled by sqrt(e_k), zero-filled tail ----
#define LOAD_CHUNK(cidx, buf)                                                  \
    do {                                                                       \
        int _base = (cidx) * CHUNK;                                            \
        for (int q = tid; q < CHUNK * 16; q += NT) {                           \
            int _row = q >> 4, _c4 = q & 15;                                   \
            float4 _v = make_float4(0.f, 0.f, 0.f, 0.f);                       \
            int _node = _base + _row;                                          \
            if (_node < n) {                                                   \
                float _sq = sqrtf(expf(g_imp[s + _node] - mx));                \
                _v = __ldg((const float4*)(x + ((size_t)(s + _node) << 6)) + _c4); \
                _v.x *= _sq; _v.y *= _sq; _v.z *= _sq; _v.w *= _sq;            \
            }                                                                  \
            *(float4*)&sz[buf][_row * RSTRIDE + _c4 * 4] = _v;                 \
        }                                                                      \
    } while (0)

    if (nch > 0) LOAD_CHUNK(0, 0);

    for (int c = 0; c < nch; ++c) {
        __syncthreads();                       // chunk c loads visible; buf (c+1)&1 free
        if (c + 1 < nch) LOAD_CHUNK(c + 1, (c + 1) & 1);

        if (isComp) {
            const float* zb = sz[c & 1];
#pragma unroll 2
            for (int k = 0; k < CHUNK / NSL; ++k) {
                int kk = k * NSL + slice;
                const float* row = zb + kk * RSTRIDE;
                float4 a0 = *(const float4*)&row[ti * 8];
                float4 a1 = *(const float4*)&row[ti * 8 + 4];
                float4 b0 = *(const float4*)&row[tj * 8];
                float4 b1 = *(const float4*)&row[tj * 8 + 4];
                float as[8] = { a0.x, a0.y, a0.z, a0.w, a1.x, a1.y, a1.z, a1.w };
                u64 ap[8], bp[4];
#pragma unroll
                for (int i = 0; i < 8; ++i)
                    asm("mov.b64 %0, {%1, %1};" : "=l"(ap[i]) : "r"(__float_as_uint(as[i])));
                asm("mov.b64 %0, {%1, %2};" : "=l"(bp[0]) : "f"(b0.x), "f"(b0.y));
                asm("mov.b64 %0, {%1, %2};" : "=l"(bp[1]) : "f"(b0.z), "f"(b0.w));
                asm("mov.b64 %0, {%1, %2};" : "=l"(bp[2]) : "f"(b1.x), "f"(b1.y));
                asm("mov.b64 %0, {%1, %2};" : "=l"(bp[3]) : "f"(b1.z), "f"(b1.w));
#pragma unroll
                for (int i = 0; i < 8; ++i)
#pragma unroll
                    for (int jp = 0; jp < 4; ++jp)
                        asm("fma.rn.f32x2 %0, %1, %2, %0;"
                            : "+l"(acc2[i][jp]) : "l"(ap[i]), "l"(bp[jp]));
            }
        }
    }

    // ---- slice combine (shfl xor 1, 2 within warp) + writeout ----
    if (isComp) {
        float accf[8][8];
#pragma unroll
        for (int i = 0; i < 8; ++i)
#pragma unroll
            for (int jp = 0; jp < 4; ++jp) {
                unsigned lo, hi;
                asm("mov.b64 {%0, %1}, %2;" : "=r"(lo), "=r"(hi) : "l"(acc2[i][jp]));
                accf[i][2 * jp]     = __uint_as_float(lo);
                accf[i][2 * jp + 1] = __uint_as_float(hi);
            }
        unsigned msk = (tid < 128) ? 0xFFFFFFFFu : 0x0000FFFFu;
#pragma unroll
        for (int i = 0; i < 8; ++i)
#pragma unroll
            for (int j = 0; j < 8; ++j) {
                accf[i][j] += __shfl_xor_sync(msk, accf[i][j], 1);
                accf[i][j] += __shfl_xor_sync(msk, accf[i][j], 2);
            }

        if (slice == 0) {
            float* og = out + (size_t)g * TRI;
#pragma unroll
            for (int i = 0; i < 8; ++i) {
                int gi = ti * 8 + i;
                int base = gi * DD - (gi * (gi - 1)) / 2 - gi;  // + gj gives triu index
#pragma unroll
                for (int j = 0; j < 8; ++j) {
                    int gj = tj * 8 + j;
                    if (gj >= gi) og[base + gj] = accf[i][j] * inv_denom;
                }
            }
        }
    }
#undef LOAD_CHUNK
}

// ---------------------------------------------------------------------------
// Launch. Inputs identified BY SIZE (order-invariant).
// ---------------------------------------------------------------------------
extern "C" void kernel_launch(void* const* d_in, const int* in_sizes, int n_in,
                              void* d_out, int out_size) {
    int ib = -1, iw = -1, ibatch = -1, ix = -1;
    for (int i = 0; i < n_in; ++i) {
        if (in_sizes[i] == 1)       ib = i;
        else if (in_sizes[i] == DD) iw = i;
    }
    for (int i = 0; i < n_in && ibatch < 0; ++i) {
        if (i == ib || i == iw) continue;
        for (int j = 0; j < n_in; ++j) {
            if (j == i || j == ib || j == iw) continue;
            if ((long long)in_sizes[i] * DD == (long long)in_sizes[j]) {
                ibatch = i; ix = j; break;
            }
        }
    }
    if (ib < 0 || iw < 0 || ibatch < 0 || ix < 0) {  // fallback: reference order
        ix = 0; iw = 1; ib = 2; ibatch = 3;
    }

    const float* x    = (const float*)d_in[ix];
    const float* w    = (const float*)d_in[iw];
    const float* bias = (const float*)d_in[ib];
    const void*  batch = d_in[ibatch];

    int M = in_sizes[ix] / DD;
    int G = out_size / TRI;
    float* out = (float*)d_out;

    k_detect<<<1, 256>>>((const int*)batch, M);
    k_bounds<<<(M + 255) / 256, 256>>>(batch, M, G);
    k_imp<<<(M * 32 + 255) / 256, 256>>>(x, w, bias, M);
    k_syrk<<<G, NT>>>(x, out, G);
}

// round 5
// speedup vs baseline: 1.0215x; 1.0215x over previous
#include <cuda_runtime.h>
#include <math.h>

#define DD      64
#define TRI     2080          // 64*65/2
#define NT      160           // threads per SYRK block (144 compute lanes)
#define NW      (NT / 32)     // 5 warps
#define CHUNK   32            // nodes per smem chunk
#define RSTRIDE 68            // padded row stride (floats)
#define NSL     4             // k-slices per tile
#define IMPCAP  512           // smem imp capacity per graph

#define MAX_M  100000
#define MAX_G  1024

__device__ float g_imp[MAX_M];         // fallback only (n > IMPCAP)
__device__ int   g_start[MAX_G + 1];
__device__ int   g_is64;

// ---------------------------------------------------------------------------
// Detect int64 vs int32 batch buffer (odd 32-bit words all zero => int64).
// ---------------------------------------------------------------------------
__global__ void k_detect(const int* __restrict__ b32, int M) {
    __shared__ int anynz;
    if (threadIdx.x == 0) anynz = 0;
    __syncthreads();
    int nwords = 2 * M;
    if (nwords > 4096) nwords = 4096;
    if (nwords > M) nwords = M;    // never exceed int32 lower-bound size
    for (int i = 2 * threadIdx.x + 1; i < nwords; i += 2 * blockDim.x)
        if (b32[i] != 0) anynz = 1;
    __syncthreads();
    if (threadIdx.x == 0) g_is64 = (anynz == 0) ? 1 : 0;
}

// ---------------------------------------------------------------------------
// Segment boundaries from sorted batch.
// ---------------------------------------------------------------------------
__global__ void k_bounds(const void* __restrict__ batch, int M, int G) {
    int m = blockIdx.x * blockDim.x + threadIdx.x;
    if (m >= M) return;
    int is64 = g_is64;
    const int* b32 = (const int*)batch;
    const long long* b64 = (const long long*)batch;
    int b  = is64 ? (int)b64[m] : b32[m];
    int pb;
    if (m == 0) pb = -1;
    else        pb = is64 ? (int)b64[m - 1] : b32[m - 1];
    if (b  < 0) b  = 0; if (b  >= G) b  = G - 1;
    if (pb < -1) pb = -1; if (pb >= G) pb = G - 1;
    for (int g = pb + 1; g <= b; ++g) g_start[g] = m;
    if (m == M - 1) {
        for (int g = b + 1; g <= G; ++g) g_start[g] = M;
    }
}

// ---------------------------------------------------------------------------
// Fused per-graph kernel: imp -> softmax stats -> weighted SYRK -> triu out.
// 36 upper 8x8 tiles x 4 k-slices = 144 compute lanes of 160.
// smem rows hold sqrt(e_k)*x_k so the pure-FFMA a*b carries e_k.
// ---------------------------------------------------------------------------
__global__ __launch_bounds__(NT, 4)
void k_syrk(const float* __restrict__ x, const float* __restrict__ w,
            const float* __restrict__ bias, float* __restrict__ out, int G) {
    __shared__ float sz[2][CHUNK * RSTRIDE];
    __shared__ float simp[IMPCAP];
    __shared__ float sred[NW];
    __shared__ float sbr[2];

    int g    = blockIdx.x;
    int tid  = threadIdx.x;
    int wid  = tid >> 5;
    int lane = tid & 31;
    int s    = g_start[g];
    int n    = g_start[g + 1] - s;
    bool useSm = (n <= IMPCAP);

    // ---- phase 1: imp for this graph's nodes (warp per node) ----
    for (int i = wid; i < n; i += NW) {
        const float* xr = x + ((size_t)(s + i) << 6);
        float v = xr[lane] * __ldg(w + lane) + xr[lane + 32] * __ldg(w + lane + 32);
#pragma unroll
        for (int o = 16; o; o >>= 1) v += __shfl_xor_sync(0xFFFFFFFFu, v, o);
        if (lane == 0) {
            float val = v + __ldg(bias);
            if (useSm) simp[i] = val;
            else       g_imp[s + i] = val;
        }
    }
    __syncthreads();

#define IMP(i) (useSm ? simp[i] : g_imp[s + (i)])

    // ---- phase 2: segment max ----
    float mx = -3.402823466e38f;
    for (int i = tid; i < n; i += NT) mx = fmaxf(mx, IMP(i));
#pragma unroll
    for (int o = 16; o; o >>= 1) mx = fmaxf(mx, __shfl_xor_sync(0xFFFFFFFFu, mx, o));
    if (lane == 0) sred[wid] = mx;
    __syncthreads();
    if (tid == 0) {
        float m2 = sred[0];
#pragma unroll
        for (int i = 1; i < NW; ++i) m2 = fmaxf(m2, sred[i]);
        sbr[0] = m2;
    }
    __syncthreads();
    mx = sbr[0];

    // ---- segment denom ----
    float sum = 0.f;
    for (int i = tid; i < n; i += NT) sum += expf(IMP(i) - mx);
#pragma unroll
    for (int o = 16; o; o >>= 1) sum += __shfl_xor_sync(0xFFFFFFFFu, sum, o);
    if (lane == 0) sred[wid] = sum;
    __syncthreads();
    if (tid == 0) {
        float t = 0.f;
#pragma unroll
        for (int i = 0; i < NW; ++i) t += sred[i];
        sbr[1] = (n > 0) ? (1.0f / t) : 0.0f;
    }
    __syncthreads();
    float inv_denom = sbr[1];

    // ---- tile mapping: tile = tid>>2 in [0,36), slice = tid&3 ----
    bool isComp = (tid < 144);
    int  tile   = tid >> 2;
    int  slice  = tid & 3;
    int  ti = 0, tmp = tile;
#pragma unroll
    for (int r = 0; r < 8; ++r) {
        int rl = 8 - r;
        if (ti == r && tmp >= rl) { tmp -= rl; ti = r + 1; }
    }
    int tj = ti + tmp;

    float acc[8][8];
#pragma unroll
    for (int i = 0; i < 8; ++i)
#pragma unroll
        for (int j = 0; j < 8; ++j) acc[i][j] = 0.f;

    int nch = (n + CHUNK - 1) / CHUNK;

    // chunk loader: rows scaled by sqrt(e_k) = exp(0.5*(imp-mx)), zero tail
#define LOAD_CHUNK(cidx, buf)                                                  \
    do {                                                                       \
        int _base = (cidx) * CHUNK;                                            \
        for (int q = tid; q < CHUNK * 16; q += NT) {                           \
            int _row = q >> 4, _c4 = q & 15;                                   \
            float4 _v = make_float4(0.f, 0.f, 0.f, 0.f);                       \
            int _node = _base + _row;                                          \
            if (_node < n) {                                                   \
                float _sq = expf(0.5f * (IMP(_node) - mx));                    \
                _v = __ldg((const float4*)(x + ((size_t)(s + _node) << 6)) + _c4); \
                _v.x *= _sq; _v.y *= _sq; _v.z *= _sq; _v.w *= _sq;            \
            }                                                                  \
            *(float4*)&sz[buf][_row * RSTRIDE + _c4 * 4] = _v;                 \
        }                                                                      \
    } while (0)

    if (nch > 0) LOAD_CHUNK(0, 0);

    for (int c = 0; c < nch; ++c) {
        __syncthreads();                       // chunk c visible; buf (c+1)&1 free
        if (c + 1 < nch) LOAD_CHUNK(c + 1, (c + 1) & 1);

        if (isComp) {
            const float* zb = sz[c & 1];
#pragma unroll
            for (int k = 0; k < CHUNK / NSL; ++k) {
                int kk = k * NSL + slice;
                const float* row = zb + kk * RSTRIDE;
                float4 a0 = *(const float4*)&row[ti * 8];
                float4 a1 = *(const float4*)&row[ti * 8 + 4];
                float4 b0 = *(const float4*)&row[tj * 8];
                float4 b1 = *(const float4*)&row[tj * 8 + 4];
                float a[8] = { a0.x, a0.y, a0.z, a0.w, a1.x, a1.y, a1.z, a1.w };
                float b[8] = { b0.x, b0.y, b0.z, b0.w, b1.x, b1.y, b1.z, b1.w };
#pragma unroll
                for (int i = 0; i < 8; ++i)
#pragma unroll
                    for (int j = 0; j < 8; ++j)
                        acc[i][j] += a[i] * b[j];
            }
        }
    }

    // ---- slice combine (shfl xor 1, 2) + triu writeout ----
    if (isComp) {
        unsigned msk = (tid < 128) ? 0xFFFFFFFFu : 0x0000FFFFu;
#pragma unroll
        for (int i = 0; i < 8; ++i)
#pragma unroll
            for (int j = 0; j < 8; ++j) {
                acc[i][j] += __shfl_xor_sync(msk, acc[i][j], 1);
                acc[i][j] += __shfl_xor_sync(msk, acc[i][j], 2);
            }

        if (slice == 0) {
            float* og = out + (size_t)g * TRI;
#pragma unroll
            for (int i = 0; i < 8; ++i) {
                int gi = ti * 8 + i;
                int base = gi * DD - (gi * (gi - 1)) / 2 - gi;  // + gj -> triu idx
#pragma unroll
                for (int j = 0; j < 8; ++j) {
                    int gj = tj * 8 + j;
                    if (gj >= gi) og[base + gj] = acc[i][j] * inv_denom;
                }
            }
        }
    }
#undef LOAD_CHUNK
#undef IMP
}

// ---------------------------------------------------------------------------
// Launch. Inputs identified BY SIZE (order-invariant):
//   att_b: size 1; att_w: size 64; batch: size*64 == size of x; edge: leftover.
// ---------------------------------------------------------------------------
extern "C" void kernel_launch(void* const* d_in, const int* in_sizes, int n_in,
                              void* d_out, int out_size) {
    int ib = -1, iw = -1, ibatch = -1, ix = -1;
    for (int i = 0; i < n_in; ++i) {
        if (in_sizes[i] == 1)       ib = i;
        else if (in_sizes[i] == DD) iw = i;
    }
    for (int i = 0; i < n_in && ibatch < 0; ++i) {
        if (i == ib || i == iw) continue;
        for (int j = 0; j < n_in; ++j) {
            if (j == i || j == ib || j == iw) continue;
            if ((long long)in_sizes[i] * DD == (long long)in_sizes[j]) {
                ibatch = i; ix = j; break;
            }
        }
    }
    if (ib < 0 || iw < 0 || ibatch < 0 || ix < 0) {  // fallback: reference order
        ix = 0; iw = 1; ib = 2; ibatch = 3;
    }

    const float* x    = (const float*)d_in[ix];
    const float* w    = (const float*)d_in[iw];
    const float* bias = (const float*)d_in[ib];
    const void*  batch = d_in[ibatch];

    int M = in_sizes[ix] / DD;
    int G = out_size / TRI;
    float* out = (float*)d_out;

    k_detect<<<1, 256>>>((const int*)batch, M);
    k_bounds<<<(M + 255) / 256, 256>>>(batch, M, G);
    k_syrk<<<G, NT>>>(x, w, bias, out, G);
}